// round 1
// baseline (speedup 1.0000x reference)
#include <cuda_runtime.h>

// WindowAttention fused kernel: one block per window (batch element).
// Pipeline (all in shared memory, fp32):
//   1. load xc = [class_token ; x[beta]]  (50 x 256) + mask[beta % 64] (50 x 50)
//   2. QKV GEMM: (50x256) @ (256x768) + bias, q scaled by 1/sqrt(32)
//   3. per-head attention (warp h <-> head h), softmax with additive mask
//   4. proj GEMM: (50x256) @ (256x256) + bias -> d_out
//
// d_out layout (reference returns (out[:,0], out[:,1:])):
//   [0, 2048*256)                 : cls outputs  (B, C)
//   [2048*256, 2048*256+2048*49*256): token outputs (B, N, C)

#define NTOK 50
#define DIM 256
#define HEADS 8
#define HEAD_DIM 32
#define BATCH 2048
#define NTHREADS 256
#define ATTN_SCALE 0.17677669529663689f   // 32^-0.5

// padded smem row strides (floats) to break bank conflicts on per-lane row loads
#define XS 260    // x / attention-output buffer stride  (260 % 32 == 4 -> 4-way max)
#define QS 772    // qkv buffer stride                    (772 % 32 == 4 -> 4-way max)

#define SMEM_FLOATS (NTOK * XS + NTOK * QS + 2500)
#define SMEM_BYTES (SMEM_FLOATS * 4)   // 216,400 bytes

__global__ void __launch_bounds__(NTHREADS, 1)
win_attn_fused_kernel(const float* __restrict__ x,
                      const float* __restrict__ mask,
                      const float* __restrict__ cls_tok,
                      const float* __restrict__ qkv_w,
                      const float* __restrict__ qkv_b,
                      const float* __restrict__ proj_w,
                      const float* __restrict__ proj_b,
                      float* __restrict__ out)
{
    extern __shared__ float smem[];
    float* s_x    = smem;                 // NTOK * XS   (reused as attention output)
    float* s_qkv  = smem + NTOK * XS;     // NTOK * QS   layout per row: [q(256) k(256) v(256)]
    float* s_mask = s_qkv + NTOK * QS;    // 2500

    const int t    = threadIdx.x;
    const int beta = blockIdx.x;

    // ---- Phase 1: load xc (cls + x) and mask into smem ----
    {
        const float* xb = x + (size_t)beta * 49 * DIM;
        for (int idx = t; idx < NTOK * DIM; idx += NTHREADS) {
            int i = idx >> 8;          // row 0..49
            int c = idx & 255;         // col 0..255
            float v = (i == 0) ? cls_tok[c] : xb[(size_t)(i - 1) * DIM + c];
            s_x[i * XS + c] = v;
        }
        const float* mrow = mask + (size_t)(beta & 63) * 2500;
        for (int idx = t; idx < 2500; idx += NTHREADS)
            s_mask[idx] = mrow[idx];
    }
    __syncthreads();

    // ---- Phase 2: QKV GEMM  C[i][c] = sum_k s_x[i][k] * qkv_w[k][c] + qkv_b[c] ----
    // 768 columns = 3 passes of 256; each thread owns one column per pass,
    // 50-row accumulator in registers. s_x reads are warp-uniform (broadcast LDS).
    #pragma unroll 1
    for (int p = 0; p < 3; ++p) {
        const int c = p * NTHREADS + t;
        float acc[NTOK];
        #pragma unroll
        for (int i = 0; i < NTOK; ++i) acc[i] = 0.0f;

        const float* wcol = qkv_w + c;
        #pragma unroll 1
        for (int k = 0; k < DIM; k += 4) {
            float w0 = wcol[(size_t)(k + 0) * 768];
            float w1 = wcol[(size_t)(k + 1) * 768];
            float w2 = wcol[(size_t)(k + 2) * 768];
            float w3 = wcol[(size_t)(k + 3) * 768];
            #pragma unroll
            for (int i = 0; i < NTOK; ++i) {
                float4 xv = *(const float4*)&s_x[i * XS + k];
                acc[i] = fmaf(xv.x, w0, acc[i]);
                acc[i] = fmaf(xv.y, w1, acc[i]);
                acc[i] = fmaf(xv.z, w2, acc[i]);
                acc[i] = fmaf(xv.w, w3, acc[i]);
            }
        }
        const float b = qkv_b[c];
        const float m = (c < 256) ? ATTN_SCALE : 1.0f;   // pre-scale q
        #pragma unroll
        for (int i = 0; i < NTOK; ++i)
            s_qkv[i * QS + c] = (acc[i] + b) * m;
    }
    __syncthreads();

    // ---- Phase 3: attention. warp h handles head h; lane owns rows lane, lane+32 ----
    {
        const int h    = t >> 5;
        const int lane = t & 31;
        const int hoff = h * HEAD_DIM;

        for (int r = lane; r < NTOK; r += 32) {
            // q row into registers (4-way bank conflict at most, once per row)
            float q[HEAD_DIM];
            const float4* qp = (const float4*)&s_qkv[r * QS + hoff];
            #pragma unroll
            for (int dq = 0; dq < 8; ++dq) {
                float4 v = qp[dq];
                q[4*dq+0] = v.x; q[4*dq+1] = v.y; q[4*dq+2] = v.z; q[4*dq+3] = v.w;
            }

            // scores (k rows are warp-uniform -> broadcast LDS)
            float s[NTOK];
            #pragma unroll
            for (int j = 0; j < NTOK; ++j) {
                const float4* kp = (const float4*)&s_qkv[j * QS + 256 + hoff];
                float a = 0.0f;
                #pragma unroll
                for (int dq = 0; dq < 8; ++dq) {
                    float4 kv = kp[dq];
                    a = fmaf(q[4*dq+0], kv.x, a);
                    a = fmaf(q[4*dq+1], kv.y, a);
                    a = fmaf(q[4*dq+2], kv.z, a);
                    a = fmaf(q[4*dq+3], kv.w, a);
                }
                s[j] = a + s_mask[r * NTOK + j];
            }

            // softmax (unnormalized exp; normalize at the end)
            float mx = s[0];
            #pragma unroll
            for (int j = 1; j < NTOK; ++j) mx = fmaxf(mx, s[j]);
            float sum = 0.0f;
            #pragma unroll
            for (int j = 0; j < NTOK; ++j) { s[j] = __expf(s[j] - mx); sum += s[j]; }
            const float inv = 1.0f / sum;

            // out = P @ V (v rows warp-uniform -> broadcast LDS)
            float o[HEAD_DIM];
            #pragma unroll
            for (int d = 0; d < HEAD_DIM; ++d) o[d] = 0.0f;
            #pragma unroll
            for (int j = 0; j < NTOK; ++j) {
                const float pj = s[j];
                const float4* vp = (const float4*)&s_qkv[j * QS + 512 + hoff];
                #pragma unroll
                for (int dq = 0; dq < 8; ++dq) {
                    float4 vv = vp[dq];
                    o[4*dq+0] = fmaf(pj, vv.x, o[4*dq+0]);
                    o[4*dq+1] = fmaf(pj, vv.y, o[4*dq+1]);
                    o[4*dq+2] = fmaf(pj, vv.z, o[4*dq+2]);
                    o[4*dq+3] = fmaf(pj, vv.w, o[4*dq+3]);
                }
            }
            // write normalized output into s_x (reused as attention-output buffer)
            #pragma unroll
            for (int dq = 0; dq < 8; ++dq) {
                *(float4*)&s_x[r * XS + hoff + 4*dq] =
                    make_float4(o[4*dq+0]*inv, o[4*dq+1]*inv, o[4*dq+2]*inv, o[4*dq+3]*inv);
            }
        }
    }
    __syncthreads();

    // ---- Phase 4: proj GEMM + store ----
    {
        const int c = t;   // 256 columns, one per thread
        float acc[NTOK];
        #pragma unroll
        for (int i = 0; i < NTOK; ++i) acc[i] = 0.0f;

        const float* wcol = proj_w + c;
        #pragma unroll 1
        for (int k = 0; k < DIM; k += 4) {
            float w0 = wcol[(size_t)(k + 0) * 256];
            float w1 = wcol[(size_t)(k + 1) * 256];
            float w2 = wcol[(size_t)(k + 2) * 256];
            float w3 = wcol[(size_t)(k + 3) * 256];
            #pragma unroll
            for (int i = 0; i < NTOK; ++i) {
                float4 xv = *(const float4*)&s_x[i * XS + k];
                acc[i] = fmaf(xv.x, w0, acc[i]);
                acc[i] = fmaf(xv.y, w1, acc[i]);
                acc[i] = fmaf(xv.z, w2, acc[i]);
                acc[i] = fmaf(xv.w, w3, acc[i]);
            }
        }
        const float pb = proj_b[c];

        // row 0 -> cls output (B, C)
        out[(size_t)beta * DIM + c] = acc[0] + pb;
        // rows 1..49 -> token output (B, 49, C)
        float* tok = out + (size_t)BATCH * DIM;
        #pragma unroll
        for (int i = 1; i < NTOK; ++i)
            tok[((size_t)beta * 49 + (i - 1)) * DIM + c] = acc[i] + pb;
    }
}

extern "C" void kernel_launch(void* const* d_in, const int* in_sizes, int n_in,
                              void* d_out, int out_size)
{
    const float* x      = (const float*)d_in[0];
    const float* mask   = (const float*)d_in[1];
    const float* cls    = (const float*)d_in[2];
    const float* qkv_w  = (const float*)d_in[3];
    const float* qkv_b  = (const float*)d_in[4];
    const float* proj_w = (const float*)d_in[5];
    const float* proj_b = (const float*)d_in[6];
    float* out = (float*)d_out;

    cudaFuncSetAttribute(win_attn_fused_kernel,
                         cudaFuncAttributeMaxDynamicSharedMemorySize, SMEM_BYTES);

    win_attn_fused_kernel<<<BATCH, NTHREADS, SMEM_BYTES>>>(
        x, mask, cls, qkv_w, qkv_b, proj_w, proj_b, out);
}